// round 3
// baseline (speedup 1.0000x reference)
#include <cuda_runtime.h>
#include <math.h>

#define B_ 64
#define T_ 32
#define R_ 49
#define E_ 512
#define V_ 30000

// ---------------- scratch (static device globals; no allocation) ----------------
__device__ float g_emb[T_*B_*E_];        // gathered embeddings, row = t*B + b
__device__ float g_X0 [T_*B_*4*E_];      // precomputed x@W_ih0^T + b_ih0 + b_hh0
__device__ float g_h0 [2][B_*E_];        // ping-pong hidden, layer 0
__device__ float g_h1 [2][B_*E_];        // ping-pong hidden, layer 1
__device__ float g_c0 [B_*E_];
__device__ float g_c1 [B_*E_];
__device__ float g_HC [B_*T_*2*E_];      // [h_top | context], row = b*T + t

// ---------------- mean over regions + LSTM state init ----------------
__global__ void k_mean_init(const float* __restrict__ f)
{
    int idx = blockIdx.x * 256 + threadIdx.x;        // over B*E
    int b = idx >> 9, e = idx & 511;
    float s = 0.f;
    #pragma unroll
    for (int r = 0; r < R_; r++) s += f[(b*R_ + r)*E_ + e];
    s *= (1.0f / R_);
    g_h0[0][idx] = s; g_h1[0][idx] = s;
    g_c0[idx] = s;    g_c1[idx] = s;
}

// ---------------- embedding gather: g_emb[(t*B+b)*E + e] ----------------
__global__ void k_embed(const int* __restrict__ cap, const float* __restrict__ table)
{
    int idx = blockIdx.x * 256 + threadIdx.x;        // over T*B*E
    int e  = idx & 511;
    int tb = idx >> 9;
    int b  = tb & 63;
    int t  = tb >> 6;
    g_emb[idx] = table[cap[b*T_ + t]*E_ + e];
}

// ---------------- generic SGEMM: C[M,N] = A[M,K] * W[N,K]^T (+bias1+bias2) ----------------
template<int BM, int BN, int BK>
__global__ __launch_bounds__(256)
void sgemm_tn(const float* __restrict__ A, int lda,
              const float* __restrict__ W, int ldw,
              float* __restrict__ C, int ldc,
              int M, int N, int K,
              const float* __restrict__ bias1,
              const float* __restrict__ bias2)
{
    constexpr int TM = 8, TN = 8;
    constexpr int THREADS = (BM/TM) * (BN/TN);       // 256
    __shared__ float As[BK][BM];
    __shared__ float Bs[BK][BN];

    const int tid = threadIdx.x;
    const int tx  = tid % (BN/TN);
    const int ty  = tid / (BN/TN);
    const int row0 = blockIdx.y * BM;
    const int col0 = blockIdx.x * BN;

    float acc[TM][TN];
    #pragma unroll
    for (int i = 0; i < TM; i++)
        #pragma unroll
        for (int j = 0; j < TN; j++) acc[i][j] = 0.f;

    for (int k0 = 0; k0 < K; k0 += BK) {
        // A tile: BM*BK floats, float4 loads
        #pragma unroll
        for (int l = 0; l < BM*BK/4/THREADS; l++) {
            int id = tid + l * THREADS;
            int r  = id / (BK/4);
            int kq = (id % (BK/4)) * 4;
            float4 v = make_float4(0.f,0.f,0.f,0.f);
            int gr = row0 + r;
            if (gr < M) v = *(const float4*)&A[(long)gr*lda + k0 + kq];
            As[kq+0][r] = v.x; As[kq+1][r] = v.y; As[kq+2][r] = v.z; As[kq+3][r] = v.w;
        }
        // W tile
        #pragma unroll
        for (int l = 0; l < BN*BK/4/THREADS; l++) {
            int id = tid + l * THREADS;
            int r  = id / (BK/4);
            int kq = (id % (BK/4)) * 4;
            float4 v = make_float4(0.f,0.f,0.f,0.f);
            int gc = col0 + r;
            if (gc < N) v = *(const float4*)&W[(long)gc*ldw + k0 + kq];
            Bs[kq+0][r] = v.x; Bs[kq+1][r] = v.y; Bs[kq+2][r] = v.z; Bs[kq+3][r] = v.w;
        }
        __syncthreads();

        #pragma unroll
        for (int kk = 0; kk < BK; kk++) {
            float a[TM], b[TN];
            #pragma unroll
            for (int i = 0; i < TM; i++) a[i] = As[kk][ty*TM + i];
            #pragma unroll
            for (int j = 0; j < TN; j++) b[j] = Bs[kk][tx*TN + j];
            #pragma unroll
            for (int i = 0; i < TM; i++)
                #pragma unroll
                for (int j = 0; j < TN; j++) acc[i][j] += a[i] * b[j];
        }
        __syncthreads();
    }

    #pragma unroll
    for (int i = 0; i < TM; i++) {
        int r = row0 + ty*TM + i;
        if (r >= M) continue;
        #pragma unroll
        for (int j = 0; j < TN; j++) {
            int cidx = col0 + tx*TN + j;
            if (cidx >= N) continue;
            float v = acc[i][j];
            if (bias1) v += bias1[cidx];
            if (bias2) v += bias2[cidx];
            C[(long)r*ldc + cidx] = v;
        }
    }
}

// ---------------- fused LSTM step (gates GEMM + cell) ----------------
// Each block handles 4 hidden units (j0..j0+3) x all 4 gates x all 64 batches.
// gates row (in weight matrix) = g*E + j ;  col index in block = g*4 + jj
__global__ __launch_bounds__(256)
void lstm_step(const float* __restrict__ x_pre,   // [B,4E] or null
               const float* __restrict__ bih,     // [4E] or null (used when x_pre null)
               const float* __restrict__ bhh,
               const float* __restrict__ hA, const float* __restrict__ WA,  // [B,E],[4E,E]
               const float* __restrict__ hB, const float* __restrict__ WB,  // optional 2nd pair
               float* __restrict__ c_state,       // [B,E] in-place
               float* __restrict__ h_out)         // [B,E]
{
    __shared__ float Hs[16][65];
    __shared__ float Ws[16][17];
    __shared__ float Gs[16][65];

    const int tid    = threadIdx.x;       // 256
    const int colIdx = tid & 15;          // 0..15 -> (gate g = col>>2, unit jj = col&3)
    const int bg     = tid >> 4;          // 0..15
    const int j0     = blockIdx.x * 4;
    const int wrow   = (colIdx >> 2) * E_ + j0 + (colIdx & 3);

    float acc[4] = {0.f, 0.f, 0.f, 0.f};

    #pragma unroll
    for (int pass = 0; pass < 2; pass++) {
        const float* h = pass ? hB : hA;
        const float* W = pass ? WB : WA;
        if (h == nullptr) break;
        for (int k0 = 0; k0 < E_; k0 += 16) {
            #pragma unroll
            for (int l = 0; l < 4; l++) {
                int id = tid + l * 256;            // 0..1023
                int b  = id >> 4, kk = id & 15;
                Hs[kk][b] = h[b*E_ + k0 + kk];
            }
            {
                int r = tid >> 4, kk = tid & 15;
                int wr = (r >> 2) * E_ + j0 + (r & 3);
                Ws[r][kk] = W[wr*E_ + k0 + kk];
            }
            __syncthreads();
            #pragma unroll
            for (int kk = 0; kk < 16; kk++) {
                float w = Ws[colIdx][kk];
                acc[0] += Hs[kk][bg     ] * w;
                acc[1] += Hs[kk][bg + 16] * w;
                acc[2] += Hs[kk][bg + 32] * w;
                acc[3] += Hs[kk][bg + 48] * w;
            }
            __syncthreads();
        }
    }

    #pragma unroll
    for (int q = 0; q < 4; q++) {
        int b = bg + q * 16;
        float base = x_pre ? x_pre[b*(4*E_) + wrow] : (bih[wrow] + bhh[wrow]);
        Gs[colIdx][b] = acc[q] + base;
    }
    __syncthreads();

    // cell update: 256 threads = 64 batches x 4 units
    {
        int b  = tid & 63;
        int j2 = tid >> 6;                 // 0..3
        float iv = Gs[     j2][b];
        float fv = Gs[ 4 + j2][b];
        float gv = Gs[ 8 + j2][b];
        float ov = Gs[12 + j2][b];
        int j = j0 + j2;
        float si = 1.f / (1.f + expf(-iv));
        float sf = 1.f / (1.f + expf(-fv));
        float so = 1.f / (1.f + expf(-ov));
        float cn = sf * c_state[b*E_ + j] + si * tanhf(gv);
        c_state[b*E_ + j] = cn;
        h_out[b*E_ + j]   = so * tanhf(cn);
    }
}

// ---------------- attention + HC write ----------------
__global__ __launch_bounds__(256)
void k_attn(const float* __restrict__ f, const float* __restrict__ h1, int t)
{
    __shared__ float hs[E_];
    __shared__ float sc[64];
    const int b   = blockIdx.x;
    const int tid = threadIdx.x;

    for (int e = tid; e < E_; e += 256) hs[e] = h1[b*E_ + e];
    __syncthreads();

    int warp = tid >> 5, lane = tid & 31;
    for (int r = warp; r < R_; r += 8) {
        const float* fr = f + (b*R_ + r)*E_;
        float p = 0.f;
        for (int e = lane; e < E_; e += 32) p += fr[e] * hs[e];
        #pragma unroll
        for (int o = 16; o; o >>= 1) p += __shfl_down_sync(0xffffffffu, p, o);
        if (lane == 0) sc[r] = p;
    }
    __syncthreads();

    if (tid == 0) {
        float m = -1e30f;
        for (int r = 0; r < R_; r++) m = fmaxf(m, sc[r]);
        float s = 0.f;
        for (int r = 0; r < R_; r++) { sc[r] = expf(sc[r] - m); s += sc[r]; }
        float inv = 1.f / s;
        for (int r = 0; r < R_; r++) sc[r] *= inv;
    }
    __syncthreads();

    float* row = g_HC + (long)(b*T_ + t) * (2*E_);
    for (int e = tid; e < E_; e += 256) {
        float ctx = 0.f;
        #pragma unroll 7
        for (int r = 0; r < R_; r++) ctx += sc[r] * f[(b*R_ + r)*E_ + e];
        row[e]      = hs[e];
        row[E_ + e] = ctx;
    }
}

// ---------------- launch ----------------
extern "C" void kernel_launch(void* const* d_in, const int* in_sizes, int n_in,
                              void* d_out, int out_size)
{
    const float* features = (const float*)d_in[0];
    const int*   captions = (const int*)  d_in[1];
    const float* embed    = (const float*)d_in[2];
    const float* W_ih     = (const float*)d_in[3];
    const float* W_hh     = (const float*)d_in[4];
    const float* b_ih     = (const float*)d_in[5];
    const float* b_hh     = (const float*)d_in[6];
    const float* W_lin    = (const float*)d_in[7];
    const float* b_lin    = (const float*)d_in[8];
    float* out = (float*)d_out;

    float *p_emb, *p_X0, *ph0, *ph1, *pc0, *pc1, *pHC;
    cudaGetSymbolAddress((void**)&p_emb, g_emb);
    cudaGetSymbolAddress((void**)&p_X0,  g_X0);
    cudaGetSymbolAddress((void**)&ph0,   g_h0);
    cudaGetSymbolAddress((void**)&ph1,   g_h1);
    cudaGetSymbolAddress((void**)&pc0,   g_c0);
    cudaGetSymbolAddress((void**)&pc1,   g_c1);
    cudaGetSymbolAddress((void**)&pHC,   g_HC);

    // 1) mean over regions -> init h/c for both layers
    k_mean_init<<<(B_*E_)/256, 256>>>(features);

    // 2) embedding gather
    k_embed<<<(T_*B_*E_)/256, 256>>>(captions, embed);

    // 3) X0 = emb @ W_ih[0]^T + b_ih[0] + b_hh[0]   (all timesteps batched)
    {
        dim3 g1((4*E_)/128, (T_*B_)/128);
        sgemm_tn<128,128,16><<<g1, 256>>>(p_emb, E_, W_ih, E_, p_X0, 4*E_,
                                          T_*B_, 4*E_, E_, b_ih, b_hh);
    }

    // 4) sequential LSTM + attention
    for (int t = 0; t < T_; t++) {
        int cur = t & 1, nxt = (t + 1) & 1;
        // layer 0: gates = X0[t] + h0 @ W_hh0^T
        lstm_step<<<E_/4, 256>>>(p_X0 + (long)t*B_*4*E_, nullptr, nullptr,
                                 ph0 + cur*B_*E_, W_hh,
                                 nullptr, nullptr,
                                 pc0, ph0 + nxt*B_*E_);
        // layer 1: gates = b + h0_new @ W_ih1^T + h1 @ W_hh1^T
        lstm_step<<<E_/4, 256>>>(nullptr, b_ih + 4*E_, b_hh + 4*E_,
                                 ph0 + nxt*B_*E_, W_ih + 4*E_*E_,
                                 ph1 + cur*B_*E_, W_hh + 4*E_*E_,
                                 pc1, ph1 + nxt*B_*E_);
        // attention over regions + write [h_top | context]
        k_attn<<<B_, 256>>>(features, ph1 + nxt*B_*E_, t);
    }

    // 5) logits = HC @ W_lin^T + b_lin   (all timesteps in one GEMM)
    {
        dim3 g2((V_ + 127)/128, (B_*T_)/128);
        sgemm_tn<128,128,16><<<g2, 256>>>(pHC, 2*E_, W_lin, 2*E_, out, V_,
                                          B_*T_, V_, 2*E_, b_lin, nullptr);
    }
}

// round 5
// speedup vs baseline: 1.0037x; 1.0037x over previous
#include <cuda_runtime.h>
#include <math.h>

#define B_ 64
#define T_ 32
#define R_ 49
#define E_ 512
#define V_ 30000

// ---------------- scratch (static device globals; no allocation) ----------------
__device__ float g_emb[T_*B_*E_];        // gathered embeddings, row = t*B + b
__device__ float g_X0 [T_*B_*4*E_];      // precomputed x@W_ih0^T + b_ih0 + b_hh0
__device__ float g_h0 [2][B_*E_];        // ping-pong hidden, layer 0
__device__ float g_h1 [2][B_*E_];        // ping-pong hidden, layer 1
__device__ float g_c0 [B_*E_];
__device__ float g_c1 [B_*E_];
__device__ float g_HC [B_*T_*2*E_];      // [h_top | context], row = b*T + t

// ---------------- mean over regions + LSTM state init ----------------
__global__ void k_mean_init(const float* __restrict__ f)
{
    int idx = blockIdx.x * 256 + threadIdx.x;        // over B*E
    int b = idx >> 9, e = idx & 511;
    float s = 0.f;
    #pragma unroll
    for (int r = 0; r < R_; r++) s += f[(b*R_ + r)*E_ + e];
    s *= (1.0f / R_);
    g_h0[0][idx] = s; g_h1[0][idx] = s;
    g_c0[idx] = s;    g_c1[idx] = s;
}

// ---------------- embedding gather: g_emb[(t*B+b)*E + e] ----------------
__global__ void k_embed(const int* __restrict__ cap, const float* __restrict__ table)
{
    int idx = blockIdx.x * 256 + threadIdx.x;        // over T*B*E
    int e  = idx & 511;
    int tb = idx >> 9;
    int b  = tb & 63;
    int t  = tb >> 6;
    g_emb[idx] = table[cap[b*T_ + t]*E_ + e];
}

// ---------------- generic SGEMM: C[M,N] = A[M,K] * W[N,K]^T (+bias1+bias2) ----------------
template<int BM, int BN, int BK>
__global__ __launch_bounds__(256)
void sgemm_tn(const float* __restrict__ A, int lda,
              const float* __restrict__ W, int ldw,
              float* __restrict__ C, int ldc,
              int M, int N, int K,
              const float* __restrict__ bias1,
              const float* __restrict__ bias2)
{
    constexpr int TM = 8, TN = 8;
    constexpr int THREADS = (BM/TM) * (BN/TN);       // 256
    __shared__ float As[BK][BM];
    __shared__ float Bs[BK][BN];

    const int tid = threadIdx.x;
    const int tx  = tid % (BN/TN);
    const int ty  = tid / (BN/TN);
    const int row0 = blockIdx.y * BM;
    const int col0 = blockIdx.x * BN;

    float acc[TM][TN];
    #pragma unroll
    for (int i = 0; i < TM; i++)
        #pragma unroll
        for (int j = 0; j < TN; j++) acc[i][j] = 0.f;

    for (int k0 = 0; k0 < K; k0 += BK) {
        // A tile: BM*BK floats, float4 loads
        #pragma unroll
        for (int l = 0; l < BM*BK/4/THREADS; l++) {
            int id = tid + l * THREADS;
            int r  = id / (BK/4);
            int kq = (id % (BK/4)) * 4;
            float4 v = make_float4(0.f,0.f,0.f,0.f);
            int gr = row0 + r;
            if (gr < M) v = *(const float4*)&A[(long)gr*lda + k0 + kq];
            As[kq+0][r] = v.x; As[kq+1][r] = v.y; As[kq+2][r] = v.z; As[kq+3][r] = v.w;
        }
        // W tile
        #pragma unroll
        for (int l = 0; l < BN*BK/4/THREADS; l++) {
            int id = tid + l * THREADS;
            int r  = id / (BK/4);
            int kq = (id % (BK/4)) * 4;
            float4 v = make_float4(0.f,0.f,0.f,0.f);
            int gc = col0 + r;
            if (gc < N) v = *(const float4*)&W[(long)gc*ldw + k0 + kq];
            Bs[kq+0][r] = v.x; Bs[kq+1][r] = v.y; Bs[kq+2][r] = v.z; Bs[kq+3][r] = v.w;
        }
        __syncthreads();

        #pragma unroll
        for (int kk = 0; kk < BK; kk++) {
            float a[TM], b[TN];
            #pragma unroll
            for (int i = 0; i < TM; i++) a[i] = As[kk][ty*TM + i];
            #pragma unroll
            for (int j = 0; j < TN; j++) b[j] = Bs[kk][tx*TN + j];
            #pragma unroll
            for (int i = 0; i < TM; i++)
                #pragma unroll
                for (int j = 0; j < TN; j++) acc[i][j] += a[i] * b[j];
        }
        __syncthreads();
    }

    #pragma unroll
    for (int i = 0; i < TM; i++) {
        int r = row0 + ty*TM + i;
        if (r >= M) continue;
        #pragma unroll
        for (int j = 0; j < TN; j++) {
            int cidx = col0 + tx*TN + j;
            if (cidx >= N) continue;
            float v = acc[i][j];
            if (bias1) v += bias1[cidx];
            if (bias2) v += bias2[cidx];
            C[(long)r*ldc + cidx] = v;
        }
    }
}

// ---------------- fused LSTM step (gates GEMM + cell) ----------------
// Each block handles 4 hidden units (j0..j0+3) x all 4 gates x all 64 batches.
// gates row (in weight matrix) = g*E + j ;  col index in block = g*4 + jj
__global__ __launch_bounds__(256)
void lstm_step(const float* __restrict__ x_pre,   // [B,4E] or null
               const float* __restrict__ bih,     // [4E] or null (used when x_pre null)
               const float* __restrict__ bhh,
               const float* __restrict__ hA, const float* __restrict__ WA,  // [B,E],[4E,E]
               const float* __restrict__ hB, const float* __restrict__ WB,  // optional 2nd pair
               float* __restrict__ c_state,       // [B,E] in-place
               float* __restrict__ h_out)         // [B,E]
{
    __shared__ float Hs[16][65];
    __shared__ float Ws[16][17];
    __shared__ float Gs[16][65];

    const int tid    = threadIdx.x;       // 256
    const int colIdx = tid & 15;          // 0..15 -> (gate g = col>>2, unit jj = col&3)
    const int bg     = tid >> 4;          // 0..15
    const int j0     = blockIdx.x * 4;
    const int wrow   = (colIdx >> 2) * E_ + j0 + (colIdx & 3);

    float acc[4] = {0.f, 0.f, 0.f, 0.f};

    #pragma unroll
    for (int pass = 0; pass < 2; pass++) {
        const float* h = pass ? hB : hA;
        const float* W = pass ? WB : WA;
        if (h == nullptr) break;
        for (int k0 = 0; k0 < E_; k0 += 16) {
            #pragma unroll
            for (int l = 0; l < 4; l++) {
                int id = tid + l * 256;            // 0..1023
                int b  = id >> 4, kk = id & 15;
                Hs[kk][b] = h[b*E_ + k0 + kk];
            }
            {
                int r = tid >> 4, kk = tid & 15;
                int wr = (r >> 2) * E_ + j0 + (r & 3);
                Ws[r][kk] = W[wr*E_ + k0 + kk];
            }
            __syncthreads();
            #pragma unroll
            for (int kk = 0; kk < 16; kk++) {
                float w = Ws[colIdx][kk];
                acc[0] += Hs[kk][bg     ] * w;
                acc[1] += Hs[kk][bg + 16] * w;
                acc[2] += Hs[kk][bg + 32] * w;
                acc[3] += Hs[kk][bg + 48] * w;
            }
            __syncthreads();
        }
    }

    #pragma unroll
    for (int q = 0; q < 4; q++) {
        int b = bg + q * 16;
        float base = x_pre ? x_pre[b*(4*E_) + wrow] : (bih[wrow] + bhh[wrow]);
        Gs[colIdx][b] = acc[q] + base;
    }
    __syncthreads();

    // cell update: 256 threads = 64 batches x 4 units
    {
        int b  = tid & 63;
        int j2 = tid >> 6;                 // 0..3
        float iv = Gs[     j2][b];
        float fv = Gs[ 4 + j2][b];
        float gv = Gs[ 8 + j2][b];
        float ov = Gs[12 + j2][b];
        int j = j0 + j2;
        float si = 1.f / (1.f + expf(-iv));
        float sf = 1.f / (1.f + expf(-fv));
        float so = 1.f / (1.f + expf(-ov));
        float cn = sf * c_state[b*E_ + j] + si * tanhf(gv);
        c_state[b*E_ + j] = cn;
        h_out[b*E_ + j]   = so * tanhf(cn);
    }
}

// ---------------- attention + HC write ----------------
__global__ __launch_bounds__(256)
void k_attn(const float* __restrict__ f, const float* __restrict__ h1, int t)
{
    __shared__ float hs[E_];
    __shared__ float sc[64];
    const int b   = blockIdx.x;
    const int tid = threadIdx.x;

    for (int e = tid; e < E_; e += 256) hs[e] = h1[b*E_ + e];
    __syncthreads();

    int warp = tid >> 5, lane = tid & 31;
    for (int r = warp; r < R_; r += 8) {
        const float* fr = f + (b*R_ + r)*E_;
        float p = 0.f;
        for (int e = lane; e < E_; e += 32) p += fr[e] * hs[e];
        #pragma unroll
        for (int o = 16; o; o >>= 1) p += __shfl_down_sync(0xffffffffu, p, o);
        if (lane == 0) sc[r] = p;
    }
    __syncthreads();

    if (tid == 0) {
        float m = -1e30f;
        for (int r = 0; r < R_; r++) m = fmaxf(m, sc[r]);
        float s = 0.f;
        for (int r = 0; r < R_; r++) { sc[r] = expf(sc[r] - m); s += sc[r]; }
        float inv = 1.f / s;
        for (int r = 0; r < R_; r++) sc[r] *= inv;
    }
    __syncthreads();

    float* row = g_HC + (long)(b*T_ + t) * (2*E_);
    for (int e = tid; e < E_; e += 256) {
        float ctx = 0.f;
        #pragma unroll 7
        for (int r = 0; r < R_; r++) ctx += sc[r] * f[(b*R_ + r)*E_ + e];
        row[e]      = hs[e];
        row[E_ + e] = ctx;
    }
}

// ---------------- launch ----------------
extern "C" void kernel_launch(void* const* d_in, const int* in_sizes, int n_in,
                              void* d_out, int out_size)
{
    const float* features = (const float*)d_in[0];
    const int*   captions = (const int*)  d_in[1];
    const float* embed    = (const float*)d_in[2];
    const float* W_ih     = (const float*)d_in[3];
    const float* W_hh     = (const float*)d_in[4];
    const float* b_ih     = (const float*)d_in[5];
    const float* b_hh     = (const float*)d_in[6];
    const float* W_lin    = (const float*)d_in[7];
    const float* b_lin    = (const float*)d_in[8];
    float* out = (float*)d_out;

    float *p_emb, *p_X0, *ph0, *ph1, *pc0, *pc1, *pHC;
    cudaGetSymbolAddress((void**)&p_emb, g_emb);
    cudaGetSymbolAddress((void**)&p_X0,  g_X0);
    cudaGetSymbolAddress((void**)&ph0,   g_h0);
    cudaGetSymbolAddress((void**)&ph1,   g_h1);
    cudaGetSymbolAddress((void**)&pc0,   g_c0);
    cudaGetSymbolAddress((void**)&pc1,   g_c1);
    cudaGetSymbolAddress((void**)&pHC,   g_HC);

    // 1) mean over regions -> init h/c for both layers
    k_mean_init<<<(B_*E_)/256, 256>>>(features);

    // 2) embedding gather
    k_embed<<<(T_*B_*E_)/256, 256>>>(captions, embed);

    // 3) X0 = emb @ W_ih[0]^T + b_ih[0] + b_hh[0]   (all timesteps batched)
    {
        dim3 g1((4*E_)/128, (T_*B_)/128);
        sgemm_tn<128,128,16><<<g1, 256>>>(p_emb, E_, W_ih, E_, p_X0, 4*E_,
                                          T_*B_, 4*E_, E_, b_ih, b_hh);
    }

    // 4) sequential LSTM + attention
    for (int t = 0; t < T_; t++) {
        int cur = t & 1, nxt = (t + 1) & 1;
        // layer 0: gates = X0[t] + h0 @ W_hh0^T
        lstm_step<<<E_/4, 256>>>(p_X0 + (long)t*B_*4*E_, nullptr, nullptr,
                                 ph0 + cur*B_*E_, W_hh,
                                 nullptr, nullptr,
                                 pc0, ph0 + nxt*B_*E_);
        // layer 1: gates = b + h0_new @ W_ih1^T + h1 @ W_hh1^T
        lstm_step<<<E_/4, 256>>>(nullptr, b_ih + 4*E_, b_hh + 4*E_,
                                 ph0 + nxt*B_*E_, W_ih + 4*E_*E_,
                                 ph1 + cur*B_*E_, W_hh + 4*E_*E_,
                                 pc1, ph1 + nxt*B_*E_);
        // attention over regions + write [h_top | context]
        k_attn<<<B_, 256>>>(features, ph1 + nxt*B_*E_, t);
    }

    // 5) logits = HC @ W_lin^T + b_lin   (all timesteps in one GEMM)
    {
        dim3 g2((V_ + 127)/128, (B_*T_)/128);
        sgemm_tn<128,128,16><<<g2, 256>>>(pHC, 2*E_, W_lin, 2*E_, out, V_,
                                          B_*T_, V_, 2*E_, b_lin, nullptr);
    }
}

// round 6
// speedup vs baseline: 1.0057x; 1.0020x over previous
#include <cuda_runtime.h>
#include <math.h>

#define B_ 64
#define T_ 32
#define R_ 49
#define E_ 512
#define V_ 30000

// ---------------- scratch (static device globals; no allocation) ----------------
__device__ float g_emb[T_*B_*E_];        // gathered embeddings, row = t*B + b
__device__ float g_X0 [T_*B_*4*E_];      // precomputed x@W_ih0^T + b_ih0 + b_hh0
__device__ float g_h0 [2][B_*E_];        // ping-pong hidden, layer 0
__device__ float g_h1 [2][B_*E_];        // ping-pong hidden, layer 1
__device__ float g_c0 [B_*E_];
__device__ float g_c1 [B_*E_];
__device__ float g_HC [B_*T_*2*E_];      // [h_top | context], row = b*T + t

// ---------------- mean over regions + LSTM state init ----------------
__global__ void k_mean_init(const float* __restrict__ f)
{
    int idx = blockIdx.x * 256 + threadIdx.x;        // over B*E
    int b = idx >> 9, e = idx & 511;
    float s = 0.f;
    #pragma unroll
    for (int r = 0; r < R_; r++) s += f[(b*R_ + r)*E_ + e];
    s *= (1.0f / R_);
    g_h0[0][idx] = s; g_h1[0][idx] = s;
    g_c0[idx] = s;    g_c1[idx] = s;
}

// ---------------- embedding gather: g_emb[(t*B+b)*E + e] ----------------
__global__ void k_embed(const int* __restrict__ cap, const float* __restrict__ table)
{
    int idx = blockIdx.x * 256 + threadIdx.x;        // over T*B*E
    int e  = idx & 511;
    int tb = idx >> 9;
    int b  = tb & 63;
    int t  = tb >> 6;
    g_emb[idx] = table[cap[b*T_ + t]*E_ + e];
}

// ---------------- generic SGEMM: C[M,N] = A[M,K] * W[N,K]^T (+bias1+bias2) ----------------
template<int BM, int BN, int BK>
__global__ __launch_bounds__(256)
void sgemm_tn(const float* __restrict__ A, int lda,
              const float* __restrict__ W, int ldw,
              float* __restrict__ C, int ldc,
              int M, int N, int K,
              const float* __restrict__ bias1,
              const float* __restrict__ bias2)
{
    constexpr int TM = 8, TN = 8;
    constexpr int THREADS = (BM/TM) * (BN/TN);       // 256
    __shared__ float As[BK][BM];
    __shared__ float Bs[BK][BN];

    const int tid = threadIdx.x;
    const int tx  = tid % (BN/TN);
    const int ty  = tid / (BN/TN);
    const int row0 = blockIdx.y * BM;
    const int col0 = blockIdx.x * BN;

    float acc[TM][TN];
    #pragma unroll
    for (int i = 0; i < TM; i++)
        #pragma unroll
        for (int j = 0; j < TN; j++) acc[i][j] = 0.f;

    for (int k0 = 0; k0 < K; k0 += BK) {
        // A tile: BM*BK floats, float4 loads
        #pragma unroll
        for (int l = 0; l < BM*BK/4/THREADS; l++) {
            int id = tid + l * THREADS;
            int r  = id / (BK/4);
            int kq = (id % (BK/4)) * 4;
            float4 v = make_float4(0.f,0.f,0.f,0.f);
            int gr = row0 + r;
            if (gr < M) v = *(const float4*)&A[(long)gr*lda + k0 + kq];
            As[kq+0][r] = v.x; As[kq+1][r] = v.y; As[kq+2][r] = v.z; As[kq+3][r] = v.w;
        }
        // W tile
        #pragma unroll
        for (int l = 0; l < BN*BK/4/THREADS; l++) {
            int id = tid + l * THREADS;
            int r  = id / (BK/4);
            int kq = (id % (BK/4)) * 4;
            float4 v = make_float4(0.f,0.f,0.f,0.f);
            int gc = col0 + r;
            if (gc < N) v = *(const float4*)&W[(long)gc*ldw + k0 + kq];
            Bs[kq+0][r] = v.x; Bs[kq+1][r] = v.y; Bs[kq+2][r] = v.z; Bs[kq+3][r] = v.w;
        }
        __syncthreads();

        #pragma unroll
        for (int kk = 0; kk < BK; kk++) {
            float a[TM], b[TN];
            #pragma unroll
            for (int i = 0; i < TM; i++) a[i] = As[kk][ty*TM + i];
            #pragma unroll
            for (int j = 0; j < TN; j++) b[j] = Bs[kk][tx*TN + j];
            #pragma unroll
            for (int i = 0; i < TM; i++)
                #pragma unroll
                for (int j = 0; j < TN; j++) acc[i][j] += a[i] * b[j];
        }
        __syncthreads();
    }

    #pragma unroll
    for (int i = 0; i < TM; i++) {
        int r = row0 + ty*TM + i;
        if (r >= M) continue;
        #pragma unroll
        for (int j = 0; j < TN; j++) {
            int cidx = col0 + tx*TN + j;
            if (cidx >= N) continue;
            float v = acc[i][j];
            if (bias1) v += bias1[cidx];
            if (bias2) v += bias2[cidx];
            C[(long)r*ldc + cidx] = v;
        }
    }
}

// ---------------- fused LSTM step (gates GEMM + cell) ----------------
// Each block handles 4 hidden units (j0..j0+3) x all 4 gates x all 64 batches.
// gates row (in weight matrix) = g*E + j ;  col index in block = g*4 + jj
__global__ __launch_bounds__(256)
void lstm_step(const float* __restrict__ x_pre,   // [B,4E] or null
               const float* __restrict__ bih,     // [4E] or null (used when x_pre null)
               const float* __restrict__ bhh,
               const float* __restrict__ hA, const float* __restrict__ WA,  // [B,E],[4E,E]
               const float* __restrict__ hB, const float* __restrict__ WB,  // optional 2nd pair
               float* __restrict__ c_state,       // [B,E] in-place
               float* __restrict__ h_out)         // [B,E]
{
    __shared__ float Hs[16][65];
    __shared__ float Ws[16][17];
    __shared__ float Gs[16][65];

    const int tid    = threadIdx.x;       // 256
    const int colIdx = tid & 15;          // 0..15 -> (gate g = col>>2, unit jj = col&3)
    const int bg     = tid >> 4;          // 0..15
    const int j0     = blockIdx.x * 4;
    const int wrow   = (colIdx >> 2) * E_ + j0 + (colIdx & 3);

    float acc[4] = {0.f, 0.f, 0.f, 0.f};

    #pragma unroll
    for (int pass = 0; pass < 2; pass++) {
        const float* h = pass ? hB : hA;
        const float* W = pass ? WB : WA;
        if (h == nullptr) break;
        for (int k0 = 0; k0 < E_; k0 += 16) {
            #pragma unroll
            for (int l = 0; l < 4; l++) {
                int id = tid + l * 256;            // 0..1023
                int b  = id >> 4, kk = id & 15;
                Hs[kk][b] = h[b*E_ + k0 + kk];
            }
            {
                int r = tid >> 4, kk = tid & 15;
                int wr = (r >> 2) * E_ + j0 + (r & 3);
                Ws[r][kk] = W[wr*E_ + k0 + kk];
            }
            __syncthreads();
            #pragma unroll
            for (int kk = 0; kk < 16; kk++) {
                float w = Ws[colIdx][kk];
                acc[0] += Hs[kk][bg     ] * w;
                acc[1] += Hs[kk][bg + 16] * w;
                acc[2] += Hs[kk][bg + 32] * w;
                acc[3] += Hs[kk][bg + 48] * w;
            }
            __syncthreads();
        }
    }

    #pragma unroll
    for (int q = 0; q < 4; q++) {
        int b = bg + q * 16;
        float base = x_pre ? x_pre[b*(4*E_) + wrow] : (bih[wrow] + bhh[wrow]);
        Gs[colIdx][b] = acc[q] + base;
    }
    __syncthreads();

    // cell update: 256 threads = 64 batches x 4 units
    {
        int b  = tid & 63;
        int j2 = tid >> 6;                 // 0..3
        float iv = Gs[     j2][b];
        float fv = Gs[ 4 + j2][b];
        float gv = Gs[ 8 + j2][b];
        float ov = Gs[12 + j2][b];
        int j = j0 + j2;
        float si = 1.f / (1.f + expf(-iv));
        float sf = 1.f / (1.f + expf(-fv));
        float so = 1.f / (1.f + expf(-ov));
        float cn = sf * c_state[b*E_ + j] + si * tanhf(gv);
        c_state[b*E_ + j] = cn;
        h_out[b*E_ + j]   = so * tanhf(cn);
    }
}

// ---------------- attention + HC write ----------------
__global__ __launch_bounds__(256)
void k_attn(const float* __restrict__ f, const float* __restrict__ h1, int t)
{
    __shared__ float hs[E_];
    __shared__ float sc[64];
    const int b   = blockIdx.x;
    const int tid = threadIdx.x;

    for (int e = tid; e < E_; e += 256) hs[e] = h1[b*E_ + e];
    __syncthreads();

    int warp = tid >> 5, lane = tid & 31;
    for (int r = warp; r < R_; r += 8) {
        const float* fr = f + (b*R_ + r)*E_;
        float p = 0.f;
        for (int e = lane; e < E_; e += 32) p += fr[e] * hs[e];
        #pragma unroll
        for (int o = 16; o; o >>= 1) p += __shfl_down_sync(0xffffffffu, p, o);
        if (lane == 0) sc[r] = p;
    }
    __syncthreads();

    if (tid == 0) {
        float m = -1e30f;
        for (int r = 0; r < R_; r++) m = fmaxf(m, sc[r]);
        float s = 0.f;
        for (int r = 0; r < R_; r++) { sc[r] = expf(sc[r] - m); s += sc[r]; }
        float inv = 1.f / s;
        for (int r = 0; r < R_; r++) sc[r] *= inv;
    }
    __syncthreads();

    float* row = g_HC + (long)(b*T_ + t) * (2*E_);
    for (int e = tid; e < E_; e += 256) {
        float ctx = 0.f;
        #pragma unroll 7
        for (int r = 0; r < R_; r++) ctx += sc[r] * f[(b*R_ + r)*E_ + e];
        row[e]      = hs[e];
        row[E_ + e] = ctx;
    }
}

// ---------------- launch ----------------
extern "C" void kernel_launch(void* const* d_in, const int* in_sizes, int n_in,
                              void* d_out, int out_size)
{
    const float* features = (const float*)d_in[0];
    const int*   captions = (const int*)  d_in[1];
    const float* embed    = (const float*)d_in[2];
    const float* W_ih     = (const float*)d_in[3];
    const float* W_hh     = (const float*)d_in[4];
    const float* b_ih     = (const float*)d_in[5];
    const float* b_hh     = (const float*)d_in[6];
    const float* W_lin    = (const float*)d_in[7];
    const float* b_lin    = (const float*)d_in[8];
    float* out = (float*)d_out;

    float *p_emb, *p_X0, *ph0, *ph1, *pc0, *pc1, *pHC;
    cudaGetSymbolAddress((void**)&p_emb, g_emb);
    cudaGetSymbolAddress((void**)&p_X0,  g_X0);
    cudaGetSymbolAddress((void**)&ph0,   g_h0);
    cudaGetSymbolAddress((void**)&ph1,   g_h1);
    cudaGetSymbolAddress((void**)&pc0,   g_c0);
    cudaGetSymbolAddress((void**)&pc1,   g_c1);
    cudaGetSymbolAddress((void**)&pHC,   g_HC);

    // 1) mean over regions -> init h/c for both layers
    k_mean_init<<<(B_*E_)/256, 256>>>(features);

    // 2) embedding gather
    k_embed<<<(T_*B_*E_)/256, 256>>>(captions, embed);

    // 3) X0 = emb @ W_ih[0]^T + b_ih[0] + b_hh[0]   (all timesteps batched)
    {
        dim3 g1((4*E_)/128, (T_*B_)/128);
        sgemm_tn<128,128,16><<<g1, 256>>>(p_emb, E_, W_ih, E_, p_X0, 4*E_,
                                          T_*B_, 4*E_, E_, b_ih, b_hh);
    }

    // 4) sequential LSTM + attention
    for (int t = 0; t < T_; t++) {
        int cur = t & 1, nxt = (t + 1) & 1;
        // layer 0: gates = X0[t] + h0 @ W_hh0^T
        lstm_step<<<E_/4, 256>>>(p_X0 + (long)t*B_*4*E_, nullptr, nullptr,
                                 ph0 + cur*B_*E_, W_hh,
                                 nullptr, nullptr,
                                 pc0, ph0 + nxt*B_*E_);
        // layer 1: gates = b + h0_new @ W_ih1^T + h1 @ W_hh1^T
        lstm_step<<<E_/4, 256>>>(nullptr, b_ih + 4*E_, b_hh + 4*E_,
                                 ph0 + nxt*B_*E_, W_ih + 4*E_*E_,
                                 ph1 + cur*B_*E_, W_hh + 4*E_*E_,
                                 pc1, ph1 + nxt*B_*E_);
        // attention over regions + write [h_top | context]
        k_attn<<<B_, 256>>>(features, ph1 + nxt*B_*E_, t);
    }

    // 5) logits = HC @ W_lin^T + b_lin   (all timesteps in one GEMM)
    {
        dim3 g2((V_ + 127)/128, (B_*T_)/128);
        sgemm_tn<128,128,16><<<g2, 256>>>(pHC, 2*E_, W_lin, 2*E_, out, V_,
                                          B_*T_, V_, 2*E_, b_lin, nullptr);
    }
}